// round 10
// baseline (speedup 1.0000x reference)
#include <cuda_runtime.h>
#include <cuda_fp16.h>
#include <cstdint>

#define BATCH 4
#define CIN   64
#define COUT  64
#define HIN   128
#define WIN   128
#define GHH   256
#define GWW   256
#define HW    (HIN * WIN)

// Scratch
__device__ float  g_kern[(size_t)BATCH * 9 * GHH * GWW];   // Gaussian affinities
__device__ __half g_wb[9 * 64 * 64];                       // per-tap B: [k][n] fp16, 128B rows, XOR-swizzled
__device__ __half g_x2[(size_t)BATCH * 129 * 129 * 64];    // x transposed [b][h][w][c] fp16, zero-padded edge

#define CP16(dst, src) asm volatile("cp.async.cg.shared.global [%0], [%1], 16;" :: "r"(dst), "l"(src))
#define CP_COMMIT()    asm volatile("cp.async.commit_group;")
#define CP_WAIT0()     asm volatile("cp.async.wait_group 0;")

// ---------------------------------------------------------------------------
// Prep: [0,1024) Gaussian kernel; [1024,1168) fp16 weights; [1168,1429) x' image
// ---------------------------------------------------------------------------
__global__ void prep_kernel(const float* __restrict__ guide,
                            const float* __restrict__ weight,
                            const float* __restrict__ x) {
    if (blockIdx.x < 1024) {
        int idx = blockIdx.x * 256 + threadIdx.x;
        int w = idx % GWW;
        int h = (idx / GWW) % GHH;
        int b = idx / (GHH * GWW);
        const float* gp = guide + (size_t)b * 3 * GHH * GWW;
        float c0 = gp[0 * GHH * GWW + h * GWW + w];
        float c1 = gp[1 * GHH * GWW + h * GWW + w];
        float c2 = gp[2 * GHH * GWW + h * GWW + w];
#pragma unroll
        for (int kh = 0; kh < 3; kh++) {
#pragma unroll
            for (int kw = 0; kw < 3; kw++) {
                if ((((h + kh) & 1) == 0) || (((w + kw) & 1) == 0)) continue;
                int hh = h + kh - 1, ww = w + kw - 1;
                float v0 = 0.f, v1 = 0.f, v2 = 0.f;
                if (hh >= 0 && hh < GHH && ww >= 0 && ww < GWW) {
                    v0 = gp[0 * GHH * GWW + hh * GWW + ww];
                    v1 = gp[1 * GHH * GWW + hh * GWW + ww];
                    v2 = gp[2 * GHH * GWW + hh * GWW + ww];
                }
                float d0 = v0 - c0, d1 = v1 - c1, d2 = v2 - c2;
                float s = d0 * d0 + d1 * d1 + d2 * d2;
                g_kern[(((size_t)b * 9 + kh * 3 + kw) * GHH + h) * GWW + w] = __expf(-0.5f * s);
            }
        }
    } else if (blockIdx.x < 1168) {
        int idx = (blockIdx.x - 1024) * 256 + threadIdx.x;
        if (idx < 9 * 64 * 64) {
            int tap = idx % 9;
            int o = (idx / 9) & 63;
            int c = idx / (9 * 64);
            float wv = weight[((size_t)c * COUT + o) * 9 + tap];
            __half bh = __float2half_rn(wv);
            char* p = (char*)g_wb + (size_t)tap * 8192;
            uint32_t col = ((uint32_t)o * 2) ^ (((uint32_t)c & 7) << 4);
            *(__half*)(p + (uint32_t)c * 128 + col) = bh;
        }
    } else {
        int idx = (blockIdx.x - 1168) * 256 + threadIdx.x;
        if (idx < BATCH * 129 * 129) {
            int b = idx / (129 * 129);
            int rem = idx % (129 * 129);
            int h = rem / 129, w = rem % 129;
            uint32_t buf[32];
            if (h < HIN && w < WIN) {
                const float* xp = x + ((size_t)b * CIN * HW) + h * WIN + w;
#pragma unroll
                for (int c = 0; c < 32; c++) {
                    __half2 p = __floats2half2_rn(xp[(size_t)(2 * c) * HW],
                                                  xp[(size_t)(2 * c + 1) * HW]);
                    buf[c] = *(uint32_t*)&p;
                }
            } else {
#pragma unroll
                for (int c = 0; c < 32; c++) buf[c] = 0u;
            }
            uint4* dst = (uint4*)(g_x2 + (size_t)idx * 64);
#pragma unroll
            for (int q = 0; q < 8; q++)
                dst[q] = make_uint4(buf[4 * q], buf[4 * q + 1], buf[4 * q + 2], buf[4 * q + 3]);
        }
    }
}

// ---------------------------------------------------------------------------
// mma helpers
// ---------------------------------------------------------------------------
__device__ __forceinline__ uint32_t smem_u32(const void* p) {
    uint32_t a;
    asm("{ .reg .u64 t; cvta.to.shared.u64 t, %1; cvt.u32.u64 %0, t; }" : "=r"(a) : "l"(p));
    return a;
}
__device__ __forceinline__ void ldsm4(uint32_t* r, uint32_t addr) {
    asm volatile("ldmatrix.sync.aligned.m8n8.x4.shared.b16 {%0,%1,%2,%3}, [%4];"
                 : "=r"(r[0]), "=r"(r[1]), "=r"(r[2]), "=r"(r[3]) : "r"(addr));
}
__device__ __forceinline__ void ldsm4t(uint32_t* r, uint32_t addr) {
    asm volatile("ldmatrix.sync.aligned.m8n8.x4.trans.shared.b16 {%0,%1,%2,%3}, [%4];"
                 : "=r"(r[0]), "=r"(r[1]), "=r"(r[2]), "=r"(r[3]) : "r"(addr));
}
__device__ __forceinline__ void mma16816(float* d, const uint32_t* a, const uint32_t* b) {
    asm volatile(
        "mma.sync.aligned.m16n8k16.row.col.f32.f16.f16.f32 "
        "{%0,%1,%2,%3}, {%4,%5,%6,%7}, {%8,%9}, {%0,%1,%2,%3};"
        : "+f"(d[0]), "+f"(d[1]), "+f"(d[2]), "+f"(d[3])
        : "r"(a[0]), "r"(a[1]), "r"(a[2]), "r"(a[3]), "r"(b[0]), "r"(b[1]));
}
__device__ __forceinline__ uint32_t hmul2(uint32_t a, uint32_t b) {
    uint32_t r;
    asm("mul.f16x2 %0, %1, %2;" : "=r"(r) : "r"(a), "r"(b));
    return r;
}

// One unit's MMA with kv folded into A fragments (fp16), accumulating into acc.
__device__ __forceinline__ void unit_mma_scaled(
    float (&acc)[2][4][4], uint32_t sb, uint32_t sB,
    uint32_t rowa, uint32_t xra, uint32_t rowb, uint32_t xrb,
    const uint32_t (&kvh)[2][2],
    uint32_t aseg, uint32_t bxr, uint32_t bseg, int lane, int wn) {
#pragma unroll
    for (int kt = 0; kt < 4; kt++) {
        uint32_t a0[4], a1[4];
        const uint32_t acol = (uint32_t)(kt * 32) + aseg;
        ldsm4(a0, rowa + (acol ^ xra));
        ldsm4(a1, rowb + (acol ^ xrb));
        a0[0] = hmul2(a0[0], kvh[0][0]); a0[1] = hmul2(a0[1], kvh[0][1]);
        a0[2] = hmul2(a0[2], kvh[0][0]); a0[3] = hmul2(a0[3], kvh[0][1]);
        a1[0] = hmul2(a1[0], kvh[1][0]); a1[1] = hmul2(a1[1], kvh[1][1]);
        a1[2] = hmul2(a1[2], kvh[1][0]); a1[3] = hmul2(a1[3], kvh[1][1]);
        const uint32_t brow = (uint32_t)(kt * 16 + (lane & 15));
#pragma unroll
        for (int np = 0; np < 2; np++) {
            uint32_t bh[4];
            const uint32_t bnb = (uint32_t)((2 * (2 * wn + np) + bseg) << 4);
            ldsm4t(bh, sB + brow * 128 + (bnb ^ bxr));
            mma16816(acc[0][2 * np],     a0, bh);
            mma16816(acc[0][2 * np + 1], a0, bh + 2);
            mma16816(acc[1][2 * np],     a1, bh);
            mma16816(acc[1][2 * np + 1], a1, bh + 2);
        }
    }
}

// SMEM: T (x-tile, 81 rows x 128B) @0; B bufs @12288/@20480; Cs overlay @0; bias @32768
#define SM_B0   12288
#define SM_BIAS 32768

// ---------------------------------------------------------------------------
// pac: block = 8h x 16w output tile (fixed h-parity, both w-parities).
//   A tap-independent from staged x-tile T (shifted ldmatrix rows); kv folded
//   into A fragments as fp16 -> HMMA accumulates directly into master acc.
//   Warp tiling 2x2: warp (wm,wn) owns m32 x n32. cp.async double-buffered B.
// ---------------------------------------------------------------------------
__global__ __launch_bounds__(128, 3)
void pac_kernel(const float* __restrict__ bias, float* __restrict__ out) {
    __shared__ __align__(256) char smem[33024];
    const uint32_t sb = smem_u32(smem);
    const int t = threadIdx.x;
    const int lane = t & 31, wid = t >> 5;
    const int wm = wid & 1, wn = wid >> 1;

    float* biasSm = (float*)(smem + SM_BIAS);
    if (t < 64) biasSm[t] = bias[t];

    // LPT: ph=1 (6 units) first, ph=0 (3 units) last
    const int bid = blockIdx.x;
    const int ph = (bid < 1024) ? 1 : 0;
    const int sub = bid & 1023;
    const int b = sub >> 8;
    const int tile = sub & 255;
    const int hh0 = (tile >> 4) * 8;
    const int ww0 = (tile & 15) * 16;

    // --- stage T: 81 rows (ih_l 0..8, iw_l 0..8) x 128B, XOR-swizzled ---
#pragma unroll
    for (int q = 0; q < 6; q++) {
        int idx = t + q * 128;
        if (idx < 648) {
            int r = idx >> 3, ck = idx & 7;
            int ihl = r / 9, iwl = r - ihl * 9;
            const __half* src = g_x2 +
                (((size_t)b * 129 + (hh0 + ihl)) * 129 + ((ww0 >> 1) + iwl)) * 64 + ck * 8;
            uint32_t dst = sb + (uint32_t)r * 128 + (((uint32_t)ck * 16) ^ (((uint32_t)(r & 7)) << 4));
            CP16(dst, src);
        }
    }
    // --- first B ---
    {
        const int tap0 = ph ? 0 : 3;
        const char* src = (const char*)g_wb + (size_t)tap0 * 8192 + t * 16;
#pragma unroll
        for (int q = 0; q < 4; q++) CP16(sb + SM_B0 + t * 16 + q * 2048, src + q * 2048);
    }
    CP_COMMIT();
    CP_WAIT0();
    __syncthreads();

    // per-lane constants
    const int pxa = 32 * wm + (lane & 15);
    const int rt0 = (pxa >> 3) * 9 + (pxa & 7);
    const int rt1 = ((pxa + 16) >> 3) * 9 + (pxa & 7);
    const uint32_t aseg = (uint32_t)((lane >> 4) << 4);
    const uint32_t bxr = (uint32_t)(((lane & 15) & 7) << 4);
    const uint32_t bseg = (uint32_t)(lane >> 4);
    const int kwcol = ww0 + 2 * (lane >> 2);  // + wpar per unit

    float acc0[2][4][4], acc1[2][4][4];
#pragma unroll
    for (int m = 0; m < 2; m++)
#pragma unroll
        for (int i = 0; i < 4; i++)
#pragma unroll
            for (int j = 0; j < 4; j++) { acc0[m][i][j] = 0.f; acc1[m][i][j] = 0.f; }

    const int nkh = ph ? 2 : 1;
    const int nunits = 3 * nkh;
    for (int ta = 0; ta < nkh; ta++) {
        const int kh = ph ? ta * 2 : 1;
        const int dh = (kh == 2) ? 1 : 0;
#pragma unroll
        for (int kwi = 0; kwi < 3; kwi++) {
            const int wpar = (kwi == 1) ? 0 : 1;
            const int dw = (kwi == 2) ? 1 : 0;
            const int tap = kh * 3 + kwi;
            const int u = ta * 3 + kwi;

            // prefetch next B into other buffer
            if (u + 1 < nunits) {
                const int ntap = (kwi == 2) ? 6 : tap + 1;
                const char* src = (const char*)g_wb + (size_t)ntap * 8192 + t * 16;
                const uint32_t dst = sb + SM_B0 + 8192 * ((u + 1) & 1) + t * 16;
#pragma unroll
                for (int q = 0; q < 4; q++) CP16(dst + q * 2048, src + q * 2048);
            }
            CP_COMMIT();

            // kv: rows hrow = 4wm + 2mt + j  ->  half2 broadcast
            const size_t kb = ((size_t)b * 9 + tap) * (GHH * GWW) + (kwcol + wpar);
            uint32_t kvh[2][2];
#pragma unroll
            for (int mt = 0; mt < 2; mt++)
#pragma unroll
                for (int j = 0; j < 2; j++) {
                    float kv = g_kern[kb + (size_t)(2 * (hh0 + 4 * wm + 2 * mt + j) + ph) * GWW];
                    __half2 h2 = __float2half2_rn(kv);
                    kvh[mt][j] = *(uint32_t*)&h2;
                }

            const uint32_t sB = sb + SM_B0 + 8192 * (u & 1);
            const int rta = rt0 + dh * 9 + dw;
            const int rtb = rt1 + dh * 9 + dw;
            const uint32_t rowa = sb + (uint32_t)rta * 128, xra = (uint32_t)((rta & 7) << 4);
            const uint32_t rowb = sb + (uint32_t)rtb * 128, xrb = (uint32_t)((rtb & 7) << 4);

            if (kwi == 1)
                unit_mma_scaled(acc0, sb, sB, rowa, xra, rowb, xrb, kvh, aseg, bxr, bseg, lane, wn);
            else
                unit_mma_scaled(acc1, sb, sB, rowa, xra, rowb, xrb, kvh, aseg, bxr, bseg, lane, wn);

            CP_WAIT0();
            __syncthreads();
        }
    }

    // --- epilogue: stage transposed to smem (swizzled), coalesced store ---
    // acc0 holds w-parity 0 (kwi==1), acc1 holds w-parity 1 (kwi==0,2)
    float* Cs = (float*)smem;
#pragma unroll
    for (int w2 = 0; w2 < 2; w2++) {
#pragma unroll
        for (int mt = 0; mt < 2; mt++) {
#pragma unroll
            for (int nt = 0; nt < 4; nt++) {
#pragma unroll
                for (int e = 0; e < 4; e++) {
                    const float v = (w2 == 0) ? acc0[mt][nt][e] : acc1[mt][nt][e];
                    const int o = 32 * wn + nt * 8 + 2 * (lane & 3) + (e & 1);
                    const int r = 32 * wm + 16 * mt + (lane >> 2) + 8 * (e >> 1);
                    const int px = (r >> 3) * 16 + 2 * (r & 7) + w2;
                    const int sw = ((o >> 1) & 1) | (((o >> 2) & 1) << 4);
                    Cs[o * 128 + (px ^ sw)] = v;
                }
            }
        }
    }
    __syncthreads();

    float* op = out + (((size_t)b * COUT) * GHH + (2 * (hh0 + (t >> 4)) + ph)) * GWW + ww0 + (t & 15);
#pragma unroll 8
    for (int o = 0; o < COUT; o++) {
        const int sw = ((o >> 1) & 1) | (((o >> 2) & 1) << 4);
        op[(size_t)o * GHH * GWW] = Cs[o * 128 + (t ^ sw)] + biasSm[o];
    }
}

// ---------------------------------------------------------------------------
extern "C" void kernel_launch(void* const* d_in, const int* in_sizes, int n_in,
                              void* d_out, int out_size) {
    const float* x      = (const float*)d_in[0];
    const float* guide  = (const float*)d_in[1];
    const float* weight = (const float*)d_in[2];
    const float* bias   = (const float*)d_in[3];
    float* out          = (float*)d_out;

    prep_kernel<<<1429, 256>>>(guide, weight, x);
    pac_kernel<<<2048, 128>>>(bias, out);
}

// round 11
// speedup vs baseline: 1.0088x; 1.0088x over previous
#include <cuda_runtime.h>
#include <cuda_fp16.h>
#include <cstdint>

#define BATCH 4
#define CIN   64
#define COUT  64
#define HIN   128
#define WIN   128
#define GHH   256
#define GWW   256
#define HW    (HIN * WIN)

// Scratch
__device__ float  g_kern[(size_t)BATCH * 9 * GHH * GWW];   // Gaussian affinities
__device__ __half g_wb[9 * 64 * 64];                       // per-tap B: [k][n] fp16, 128B rows, XOR-swizzled
__device__ __half g_x2[(size_t)BATCH * 129 * 129 * 64];    // x transposed [b][h][w][c] fp16, zero-padded edge

#define CP16(dst, src) asm volatile("cp.async.cg.shared.global [%0], [%1], 16;" :: "r"(dst), "l"(src))
#define CP_COMMIT()    asm volatile("cp.async.commit_group;")
#define CP_WAIT0()     asm volatile("cp.async.wait_group 0;")

// Dynamic SMEM layout: T @0 (81 rows x 128B = 10368); B slots @10368 (6 x 8192);
// bias @59520; total 59776. Epilogue Cs (32KB) overlays T+B.
#define SM_B    10368
#define SM_BIAS 59520
#define SM_TOT  59776

// ---------------------------------------------------------------------------
// Prep: [0,1024) Gaussian kernel; [1024,1168) fp16 weights; [1168,1429) x' image
// ---------------------------------------------------------------------------
__global__ void prep_kernel(const float* __restrict__ guide,
                            const float* __restrict__ weight,
                            const float* __restrict__ x) {
    if (blockIdx.x < 1024) {
        int idx = blockIdx.x * 256 + threadIdx.x;
        int w = idx % GWW;
        int h = (idx / GWW) % GHH;
        int b = idx / (GHH * GWW);
        const float* gp = guide + (size_t)b * 3 * GHH * GWW;
        float c0 = gp[0 * GHH * GWW + h * GWW + w];
        float c1 = gp[1 * GHH * GWW + h * GWW + w];
        float c2 = gp[2 * GHH * GWW + h * GWW + w];
#pragma unroll
        for (int kh = 0; kh < 3; kh++) {
#pragma unroll
            for (int kw = 0; kw < 3; kw++) {
                if ((((h + kh) & 1) == 0) || (((w + kw) & 1) == 0)) continue;
                int hh = h + kh - 1, ww = w + kw - 1;
                float v0 = 0.f, v1 = 0.f, v2 = 0.f;
                if (hh >= 0 && hh < GHH && ww >= 0 && ww < GWW) {
                    v0 = gp[0 * GHH * GWW + hh * GWW + ww];
                    v1 = gp[1 * GHH * GWW + hh * GWW + ww];
                    v2 = gp[2 * GHH * GWW + hh * GWW + ww];
                }
                float d0 = v0 - c0, d1 = v1 - c1, d2 = v2 - c2;
                float s = d0 * d0 + d1 * d1 + d2 * d2;
                g_kern[(((size_t)b * 9 + kh * 3 + kw) * GHH + h) * GWW + w] = __expf(-0.5f * s);
            }
        }
    } else if (blockIdx.x < 1168) {
        int idx = (blockIdx.x - 1024) * 256 + threadIdx.x;
        if (idx < 9 * 64 * 64) {
            int tap = idx % 9;
            int o = (idx / 9) & 63;
            int c = idx / (9 * 64);
            float wv = weight[((size_t)c * COUT + o) * 9 + tap];
            __half bh = __float2half_rn(wv);
            char* p = (char*)g_wb + (size_t)tap * 8192;
            uint32_t col = ((uint32_t)o * 2) ^ (((uint32_t)c & 7) << 4);
            *(__half*)(p + (uint32_t)c * 128 + col) = bh;
        }
    } else {
        int idx = (blockIdx.x - 1168) * 256 + threadIdx.x;
        if (idx < BATCH * 129 * 129) {
            int b = idx / (129 * 129);
            int rem = idx % (129 * 129);
            int h = rem / 129, w = rem % 129;
            uint32_t buf[32];
            if (h < HIN && w < WIN) {
                const float* xp = x + ((size_t)b * CIN * HW) + h * WIN + w;
#pragma unroll
                for (int c = 0; c < 32; c++) {
                    __half2 p = __floats2half2_rn(xp[(size_t)(2 * c) * HW],
                                                  xp[(size_t)(2 * c + 1) * HW]);
                    buf[c] = *(uint32_t*)&p;
                }
            } else {
#pragma unroll
                for (int c = 0; c < 32; c++) buf[c] = 0u;
            }
            uint4* dst = (uint4*)(g_x2 + (size_t)idx * 64);
#pragma unroll
            for (int q = 0; q < 8; q++)
                dst[q] = make_uint4(buf[4 * q], buf[4 * q + 1], buf[4 * q + 2], buf[4 * q + 3]);
        }
    }
}

// ---------------------------------------------------------------------------
// mma helpers
// ---------------------------------------------------------------------------
__device__ __forceinline__ uint32_t smem_u32(const void* p) {
    uint32_t a;
    asm("{ .reg .u64 t; cvta.to.shared.u64 t, %1; cvt.u32.u64 %0, t; }" : "=r"(a) : "l"(p));
    return a;
}
__device__ __forceinline__ void ldsm4(uint32_t* r, uint32_t addr) {
    asm volatile("ldmatrix.sync.aligned.m8n8.x4.shared.b16 {%0,%1,%2,%3}, [%4];"
                 : "=r"(r[0]), "=r"(r[1]), "=r"(r[2]), "=r"(r[3]) : "r"(addr));
}
__device__ __forceinline__ void ldsm4t(uint32_t* r, uint32_t addr) {
    asm volatile("ldmatrix.sync.aligned.m8n8.x4.trans.shared.b16 {%0,%1,%2,%3}, [%4];"
                 : "=r"(r[0]), "=r"(r[1]), "=r"(r[2]), "=r"(r[3]) : "r"(addr));
}
__device__ __forceinline__ void mma16816(float* d, const uint32_t* a, const uint32_t* b) {
    asm volatile(
        "mma.sync.aligned.m16n8k16.row.col.f32.f16.f16.f32 "
        "{%0,%1,%2,%3}, {%4,%5,%6,%7}, {%8,%9}, {%0,%1,%2,%3};"
        : "+f"(d[0]), "+f"(d[1]), "+f"(d[2]), "+f"(d[3])
        : "r"(a[0]), "r"(a[1]), "r"(a[2]), "r"(a[3]), "r"(b[0]), "r"(b[1]));
}
__device__ __forceinline__ uint32_t hmul2(uint32_t a, uint32_t b) {
    uint32_t r;
    asm("mul.f16x2 %0, %1, %2;" : "=r"(r) : "r"(a), "r"(b));
    return r;
}

// One unit's MMA with kv folded into A fragments (fp16), accumulating into acc.
__device__ __forceinline__ void unit_mma_scaled(
    float (&acc)[2][4][4], uint32_t sB,
    uint32_t rowa, uint32_t xra, uint32_t rowb, uint32_t xrb,
    const uint32_t (&kvh)[2][2],
    uint32_t aseg, uint32_t bxr, uint32_t bseg, int lane, int wn) {
#pragma unroll
    for (int kt = 0; kt < 4; kt++) {
        uint32_t a0[4], a1[4];
        const uint32_t acol = (uint32_t)(kt * 32) + aseg;
        ldsm4(a0, rowa + (acol ^ xra));
        ldsm4(a1, rowb + (acol ^ xrb));
        a0[0] = hmul2(a0[0], kvh[0][0]); a0[1] = hmul2(a0[1], kvh[0][1]);
        a0[2] = hmul2(a0[2], kvh[0][0]); a0[3] = hmul2(a0[3], kvh[0][1]);
        a1[0] = hmul2(a1[0], kvh[1][0]); a1[1] = hmul2(a1[1], kvh[1][1]);
        a1[2] = hmul2(a1[2], kvh[1][0]); a1[3] = hmul2(a1[3], kvh[1][1]);
        const uint32_t brow = (uint32_t)(kt * 16 + (lane & 15));
#pragma unroll
        for (int np = 0; np < 2; np++) {
            uint32_t bh[4];
            const uint32_t bnb = (uint32_t)((2 * (2 * wn + np) + bseg) << 4);
            ldsm4t(bh, sB + brow * 128 + (bnb ^ bxr));
            mma16816(acc[0][2 * np],     a0, bh);
            mma16816(acc[0][2 * np + 1], a0, bh + 2);
            mma16816(acc[1][2 * np],     a1, bh);
            mma16816(acc[1][2 * np + 1], a1, bh + 2);
        }
    }
}

// ---------------------------------------------------------------------------
// pac: block = 8h x 16w output tile (fixed h-parity, both w-parities).
//   ALL B tiles + x-tile T staged behind ONE sync; unit loop is barrier-free
//   per-warp ldsm+mma (warps drift freely). kv folded into A frags as fp16.
// ---------------------------------------------------------------------------
__global__ __launch_bounds__(128, 3)
void pac_kernel(const float* __restrict__ bias, float* __restrict__ out) {
    extern __shared__ __align__(256) char smem[];
    const uint32_t sb = smem_u32(smem);
    const int t = threadIdx.x;
    const int lane = t & 31, wid = t >> 5;
    const int wm = wid & 1, wn = wid >> 1;

    float* biasSm = (float*)(smem + SM_BIAS);
    if (t < 64) biasSm[t] = bias[t];

    // LPT: ph=1 (6 units) first, ph=0 (3 units) last
    const int bid = blockIdx.x;
    const int ph = (bid < 1024) ? 1 : 0;
    const int sub = bid & 1023;
    const int b = sub >> 8;
    const int tile = sub & 255;
    const int hh0 = (tile >> 4) * 8;
    const int ww0 = (tile & 15) * 16;

    // --- stage T: 81 rows (ih_l 0..8, iw_l 0..8) x 128B, XOR-swizzled ---
#pragma unroll
    for (int q = 0; q < 6; q++) {
        int idx = t + q * 128;
        if (idx < 648) {
            int r = idx >> 3, ck = idx & 7;
            int ihl = r / 9, iwl = r - ihl * 9;
            const __half* src = g_x2 +
                (((size_t)b * 129 + (hh0 + ihl)) * 129 + ((ww0 >> 1) + iwl)) * 64 + ck * 8;
            uint32_t dst = sb + (uint32_t)r * 128 + (((uint32_t)ck * 16) ^ (((uint32_t)(r & 7)) << 4));
            CP16(dst, src);
        }
    }
    // --- stage ALL B tiles for this block's units (slot u = ta*3+kwi) ---
    {
        const int nkh_ = ph ? 2 : 1;
        for (int u = 0; u < 3 * nkh_; u++) {
            const int kh_ = ph ? (u / 3) * 2 : 1;
            const int tap_ = kh_ * 3 + (u % 3);
            const char* src = (const char*)g_wb + (size_t)tap_ * 8192 + t * 16;
            const uint32_t dst = sb + SM_B + (uint32_t)u * 8192 + t * 16;
#pragma unroll
            for (int q = 0; q < 4; q++) CP16(dst + q * 2048, src + q * 2048);
        }
    }
    CP_COMMIT();
    CP_WAIT0();
    __syncthreads();

    // per-lane constants
    const int pxa = 32 * wm + (lane & 15);
    const int rt0 = (pxa >> 3) * 9 + (pxa & 7);
    const int rt1 = ((pxa + 16) >> 3) * 9 + (pxa & 7);
    const uint32_t aseg = (uint32_t)((lane >> 4) << 4);
    const uint32_t bxr = (uint32_t)(((lane & 15) & 7) << 4);
    const uint32_t bseg = (uint32_t)(lane >> 4);
    const int kwcol = ww0 + 2 * (lane >> 2);  // + wpar per unit

    float acc0[2][4][4], acc1[2][4][4];
#pragma unroll
    for (int m = 0; m < 2; m++)
#pragma unroll
        for (int i = 0; i < 4; i++)
#pragma unroll
            for (int j = 0; j < 4; j++) { acc0[m][i][j] = 0.f; acc1[m][i][j] = 0.f; }

    const int nkh = ph ? 2 : 1;
    for (int ta = 0; ta < nkh; ta++) {
        const int kh = ph ? ta * 2 : 1;
        const int dh = (kh == 2) ? 1 : 0;
#pragma unroll
        for (int kwi = 0; kwi < 3; kwi++) {
            const int wpar = (kwi == 1) ? 0 : 1;
            const int dw = (kwi == 2) ? 1 : 0;
            const int tap = kh * 3 + kwi;
            const int u = ta * 3 + kwi;

            // kv: rows hrow = 4wm + 2mt + j  ->  half2 broadcast
            const size_t kb = ((size_t)b * 9 + tap) * (GHH * GWW) + (kwcol + wpar);
            uint32_t kvh[2][2];
#pragma unroll
            for (int mt = 0; mt < 2; mt++)
#pragma unroll
                for (int j = 0; j < 2; j++) {
                    float kv = g_kern[kb + (size_t)(2 * (hh0 + 4 * wm + 2 * mt + j) + ph) * GWW];
                    __half2 h2 = __float2half2_rn(kv);
                    kvh[mt][j] = *(uint32_t*)&h2;
                }

            const uint32_t sB = sb + SM_B + (uint32_t)u * 8192;
            const int rta = rt0 + dh * 9 + dw;
            const int rtb = rt1 + dh * 9 + dw;
            const uint32_t rowa = sb + (uint32_t)rta * 128, xra = (uint32_t)((rta & 7) << 4);
            const uint32_t rowb = sb + (uint32_t)rtb * 128, xrb = (uint32_t)((rtb & 7) << 4);

            if (kwi == 1)
                unit_mma_scaled(acc0, sB, rowa, xra, rowb, xrb, kvh, aseg, bxr, bseg, lane, wn);
            else
                unit_mma_scaled(acc1, sB, rowa, xra, rowb, xrb, kvh, aseg, bxr, bseg, lane, wn);
        }
    }

    // --- epilogue: stage transposed to smem (swizzled), coalesced store ---
    // acc0 holds w-parity 0 (kwi==1), acc1 holds w-parity 1 (kwi==0,2)
    __syncthreads();
    float* Cs = (float*)smem;
#pragma unroll
    for (int w2 = 0; w2 < 2; w2++) {
#pragma unroll
        for (int mt = 0; mt < 2; mt++) {
#pragma unroll
            for (int nt = 0; nt < 4; nt++) {
#pragma unroll
                for (int e = 0; e < 4; e++) {
                    const float v = (w2 == 0) ? acc0[mt][nt][e] : acc1[mt][nt][e];
                    const int o = 32 * wn + nt * 8 + 2 * (lane & 3) + (e & 1);
                    const int r = 32 * wm + 16 * mt + (lane >> 2) + 8 * (e >> 1);
                    const int px = (r >> 3) * 16 + 2 * (r & 7) + w2;
                    const int sw = ((o >> 1) & 1) | (((o >> 2) & 1) << 4);
                    Cs[o * 128 + (px ^ sw)] = v;
                }
            }
        }
    }
    __syncthreads();

    float* op = out + (((size_t)b * COUT) * GHH + (2 * (hh0 + (t >> 4)) + ph)) * GWW + ww0 + (t & 15);
#pragma unroll 8
    for (int o = 0; o < COUT; o++) {
        const int sw = ((o >> 1) & 1) | (((o >> 2) & 1) << 4);
        op[(size_t)o * GHH * GWW] = Cs[o * 128 + (t ^ sw)] + biasSm[o];
    }
}

// ---------------------------------------------------------------------------
extern "C" void kernel_launch(void* const* d_in, const int* in_sizes, int n_in,
                              void* d_out, int out_size) {
    const float* x      = (const float*)d_in[0];
    const float* guide  = (const float*)d_in[1];
    const float* weight = (const float*)d_in[2];
    const float* bias   = (const float*)d_in[3];
    float* out          = (float*)d_out;

    cudaFuncSetAttribute(pac_kernel, cudaFuncAttributeMaxDynamicSharedMemorySize, SM_TOT);

    prep_kernel<<<1429, 256>>>(guide, weight, x);
    pac_kernel<<<2048, 128, SM_TOT>>>(bias, out);
}